// round 15
// baseline (speedup 1.0000x reference)
#include <cuda_runtime.h>
#include <cstdint>

static constexpr int N    = 1024;
static constexpr int EMAX = 524288;
static constexpr int HB   = 256;   // histogram blocks

// ---------------- device scratch ----------------
__device__ int   g_is64;
__device__ int   g_bh[HB * N];
__device__ int   g_tot[N];
__device__ int   g_base[N];
__device__ int   g_off[N + 1];
__device__ int   g_src[EMAX];
__device__ float g_A1[N * 64];
__device__ float g_B1[N * 64];
__device__ float g_A2[N * 64];
__device__ float g_B2[N * 64];
__device__ float g_h2[N * 512];

__device__ __forceinline__ float neg_inf() { return __int_as_float(0xff800000); }

// pack two fp32 into fp16x2: lo -> low half, hi -> high half
__device__ __forceinline__ uint32_t pack_h2(float lo, float hi) {
    uint32_t r;
    asm("cvt.rn.f16x2.f32 %0, %1, %2;" : "=r"(r) : "f"(hi), "f"(lo));
    return r;
}

__device__ __forceinline__ void mma_f16(float d[4], const uint4& a,
                                        const uint32_t b[2]) {
    asm volatile(
        "mma.sync.aligned.m16n8k16.row.col.f32.f16.f16.f32 "
        "{%0,%1,%2,%3}, {%4,%5,%6,%7}, {%8,%9}, {%0,%1,%2,%3};"
        : "+f"(d[0]), "+f"(d[1]), "+f"(d[2]), "+f"(d[3])
        : "r"(a.x), "r"(a.y), "r"(a.z), "r"(a.w), "r"(b[0]), "r"(b[1]));
}

// ---------------- sort pipeline ----------------
__device__ __forceinline__ int edge_val(const void* p, long long i, int is64) {
    if (is64) return (int)((const long long*)p)[i];
    return ((const int*)p)[i];
}

// Parallel dtype detect: 64 threads, one coalesced load each, ballot-combine.
// (The old 1-thread loop with `break` serialized ~64 DRAM latencies ≈ 15+ us.)
__global__ void k_detect(const void* edges) {
    const long long* q = (const long long*)edges;
    long long v = q[threadIdx.x];
    int bad = (v < 0 || v >= N) ? 1 : 0;
    unsigned m = __ballot_sync(0xffffffffu, bad);
    __shared__ int anybad[2];
    if ((threadIdx.x & 31) == 0) anybad[threadIdx.x >> 5] = (m != 0);
    __syncthreads();
    if (threadIdx.x == 0) g_is64 = !(anybad[0] | anybad[1]);
}

__global__ void k_hist2(const void* edges, int E) {
    __shared__ int h[N];
    int b = blockIdx.x, tid = threadIdx.x;
    for (int i = tid; i < N; i += 512) h[i] = 0;
    __syncthreads();
    int is64 = g_is64;
    int per = (E + HB - 1) / HB;
    int s0 = b * per, s1 = min(E, s0 + per);
    for (int base = s0; base < s1; base += 4096) {
        int d[8];
#pragma unroll
        for (int j = 0; j < 8; j++) {
            int e = base + tid + j * 512;
            d[j] = (e < s1) ? edge_val(edges, (long long)E + e, is64) : -1;
        }
#pragma unroll
        for (int j = 0; j < 8; j++)
            if (d[j] >= 0) atomicAdd(&h[d[j]], 1);
    }
    __syncthreads();
    for (int i = tid; i < N; i += 512) g_bh[b * N + i] = h[i];
}

// per-dst exclusive scan over the HB block-histograms.
__global__ void k_scanA() {
    __shared__ int s[16][32];
    int tid = threadIdx.x;
    int dlane = tid & 31, bg = tid >> 5;
    int d = blockIdx.x * 32 + dlane;
    int v[16], sum = 0;
#pragma unroll
    for (int j = 0; j < 16; j++) v[j] = g_bh[(bg * 16 + j) * N + d];
#pragma unroll
    for (int j = 0; j < 16; j++) { int t = v[j]; v[j] = sum; sum += t; }
    s[bg][dlane] = sum;
    __syncthreads();
    int base = 0;
#pragma unroll
    for (int k = 0; k < 16; k++) {
        int val = s[k][dlane];
        if (k < bg) base += val;
    }
    if (bg == 15) g_tot[d] = base + sum;
#pragma unroll
    for (int j = 0; j < 16; j++) g_bh[(bg * 16 + j) * N + d] = base + v[j];
}

__global__ void k_scanB() {
    __shared__ int s[N];
    int d = threadIdx.x;
    int tot = g_tot[d];
    s[d] = tot;
    __syncthreads();
    for (int off = 1; off < N; off <<= 1) {
        int v = (d >= off) ? s[d - off] : 0;
        __syncthreads();
        s[d] += v;
        __syncthreads();
    }
    g_off[d + 1] = s[d];
    if (d == 0) g_off[0] = 0;
    g_base[d] = s[d] - tot;
}

__global__ void k_scatter2(const void* edges, int E) {
    __shared__ int h[N];
    __shared__ int bhs[N];
    int b = blockIdx.x, tid = threadIdx.x;
    for (int i = tid; i < N; i += 512) {
        h[i] = 0;
        bhs[i] = g_base[i] + g_bh[b * N + i];
    }
    __syncthreads();
    int is64 = g_is64;
    int per = (E + HB - 1) / HB;
    int s0 = b * per, s1 = min(E, s0 + per);
    for (int base = s0; base < s1; base += 4096) {
        int d[8], sv[8];
#pragma unroll
        for (int j = 0; j < 8; j++) {
            int e = base + tid + j * 512;
            if (e < s1) {
                sv[j] = edge_val(edges, e, is64);
                d[j]  = edge_val(edges, (long long)E + e, is64);
            } else d[j] = -1;
        }
#pragma unroll
        for (int j = 0; j < 8; j++)
            if (d[j] >= 0) {
                int pos = bhs[d[j]] + atomicAdd(&h[d[j]], 1);
                g_src[pos] = sv[j];
            }
    }
}

// ---------------- per-node A/B precompute (layer 1) ----------------
__global__ void k_pre1(const float* __restrict__ x, const float* __restrict__ W1,
                       const float* __restrict__ b1) {
    __shared__ float xr[64];
    int n = blockIdx.x, j = threadIdx.x;
    xr[j] = x[n * 64 + j];
    __syncthreads();
    float a = b1[j], b = 0.f;
#pragma unroll 8
    for (int k = 0; k < 64; k++) {
        float xv = xr[k];
        a = fmaf(xv, W1[k * 64 + j], a);
        b = fmaf(xv, W1[(64 + k) * 64 + j], b);
    }
    g_A1[n * 64 + j] = a;
    g_B1[n * 64 + j] = b;
}

// ---------------- tensor-core (mma.sync fp16 m16n8k16) EdgeConv ----------------
// 256 threads = 8 warps per CTA; MAXCTA CTAs co-resident per SM so one CTA's
// MMAs cover another CTA's gather/build stalls.
// SPLIT = channel-split CTAs per node (conv2: 2, each owning C_OUT/SPLIT chans).
// P tile (128 edges x 64 k, fp16) fragment-major, double-buffered:
//   uint4 slot [buf*1024 + (m*32+L)*4 + ((s+(L>>1))&3)]; rotation =>
//   conflict-free STS.128 / LDS.128.
// FUSE: epilogue computes A2/B2 = f(h1[n]) in-place (fused pre2).
template <int C_OUT, int EG, int SPLIT, bool FUSE, int MAXCTA>
__global__ void __launch_bounds__(256, MAXCTA)
k_conv_mma(const float* __restrict__ Avec, const float* __restrict__ Bvec,
           const float* __restrict__ W, const float* __restrict__ bias,
           float* __restrict__ out, float* __restrict__ outB,
           const float* __restrict__ W3, const float* __restrict__ b3) {
    constexpr int THREADS = 256;
    constexpr int CPC = C_OUT / SPLIT;
    constexpr int CG  = 8 / EG;
    constexpr int NT  = (CPC / CG) / 8;
    __shared__ __align__(16) uint4 Ps4[2048];
    __shared__ __align__(16) float avs[64];
    __shared__ float red[(EG > 1 ? EG : 1) * CPC];
    __shared__ float hs[FUSE ? 128 : 1];

    int tid = threadIdx.x, lane = tid & 31;
    int wid = tid >> 5;
    int g = lane >> 2, tig = lane & 3;
    int cgrp = wid / EG, egrp = wid % EG;
    int n = blockIdx.x / SPLIT;
    int csplit = blockIdx.x % SPLIT;
    int cbase = csplit * CPC + cgrp * (NT * 8);

    if (tid < 64) avs[tid] = Avec[n * 64 + tid];

    uint32_t wf[4][NT][2];
#pragma unroll
    for (int s = 0; s < 4; s++)
#pragma unroll
        for (int t = 0; t < NT; t++) {
            int c = cbase + t * 8 + g;
            int k0 = s * 16 + 2 * tig;
            wf[s][t][0] = pack_h2(W[k0 * C_OUT + c], W[(k0 + 1) * C_OUT + c]);
            wf[s][t][1] = pack_h2(W[(k0 + 8) * C_OUT + c], W[(k0 + 9) * C_OUT + c]);
        }

    float mx[NT][2];
#pragma unroll
    for (int t = 0; t < NT; t++) { mx[t][0] = neg_inf(); mx[t][1] = neg_inf(); }

    int beg = g_off[n], end = g_off[n + 1];

    auto build = [&](int bufi, int t0, int cnt) {
#pragma unroll
        for (int it = 0; it < 4; it++) {
            int idx = tid + it * THREADS;
            int m = idx >> 7, s = (idx >> 5) & 3, L = idx & 31;
            if (m * 16 < cnt) {
                int gg = L >> 2, tt = L & 3;
                int e0 = m * 16 + gg;
                int i0 = min(t0 + e0, end - 1);
                int i1 = min(t0 + e0 + 8, end - 1);
                const float* B0 = Bvec + g_src[i0] * 64;
                const float* B1 = Bvec + g_src[i1] * 64;
                int k0 = s * 16 + 2 * tt;
                float2 a0 = *(const float2*)(avs + k0);
                float2 a1 = *(const float2*)(avs + k0 + 8);
                float2 p0 = *(const float2*)(B0 + k0);
                float2 p1 = *(const float2*)(B1 + k0);
                float2 q0 = *(const float2*)(B0 + k0 + 8);
                float2 q1 = *(const float2*)(B1 + k0 + 8);
                uint4 v;
                v.x = pack_h2(fmaxf(a0.x + p0.x, 0.f), fmaxf(a0.y + p0.y, 0.f));
                v.y = pack_h2(fmaxf(a0.x + p1.x, 0.f), fmaxf(a0.y + p1.y, 0.f));
                v.z = pack_h2(fmaxf(a1.x + q0.x, 0.f), fmaxf(a1.y + q0.y, 0.f));
                v.w = pack_h2(fmaxf(a1.x + q1.x, 0.f), fmaxf(a1.y + q1.y, 0.f));
                Ps4[bufi * 1024 + (m * 32 + L) * 4 + ((s + (L >> 1)) & 3)] = v;
            }
        }
    };

    __syncthreads();
    if (beg < end) build(0, beg, min(128, end - beg));
    __syncthreads();

    int buf = 0;
    for (int t0 = beg; t0 < end; t0 += 128, buf ^= 1) {
        int cnt = min(128, end - t0);
        for (int m = egrp; m < 8; m += EG) {
            if (m * 16 >= cnt) break;
            float acc4[NT][4];
#pragma unroll
            for (int t = 0; t < NT; t++) {
                acc4[t][0] = 0.f; acc4[t][1] = 0.f;
                acc4[t][2] = 0.f; acc4[t][3] = 0.f;
            }
#pragma unroll
            for (int s = 0; s < 4; s++) {
                uint4 q = Ps4[buf * 1024 + (m * 32 + lane) * 4 + ((s + (lane >> 1)) & 3)];
#pragma unroll
                for (int t = 0; t < NT; t++) mma_f16(acc4[t], q, wf[s][t]);
            }
            int r0 = m * 16 + g;
            bool v0 = r0 < cnt, v1 = (r0 + 8) < cnt;
#pragma unroll
            for (int t = 0; t < NT; t++) {
                if (v0) { mx[t][0] = fmaxf(mx[t][0], acc4[t][0]);
                          mx[t][1] = fmaxf(mx[t][1], acc4[t][1]); }
                if (v1) { mx[t][0] = fmaxf(mx[t][0], acc4[t][2]);
                          mx[t][1] = fmaxf(mx[t][1], acc4[t][3]); }
            }
        }
        int nt0 = t0 + 128;
        if (nt0 < end) build(buf ^ 1, nt0, min(128, end - nt0));
        __syncthreads();
    }

#pragma unroll
    for (int t = 0; t < NT; t++)
#pragma unroll
        for (int off = 4; off < 32; off <<= 1) {
            mx[t][0] = fmaxf(mx[t][0], __shfl_xor_sync(0xffffffffu, mx[t][0], off));
            mx[t][1] = fmaxf(mx[t][1], __shfl_xor_sync(0xffffffffu, mx[t][1], off));
        }

    if (EG == 1) {
        if (lane < 4) {
#pragma unroll
            for (int t = 0; t < NT; t++) {
                int c = cbase + t * 8 + 2 * tig;
                float v0 = mx[t][0], v1 = mx[t][1];
                out[n * C_OUT + c]     = (v0 == neg_inf()) ? 0.f : v0 + bias[c];
                out[n * C_OUT + c + 1] = (v1 == neg_inf()) ? 0.f : v1 + bias[c + 1];
            }
        }
    } else {
        if (lane < 4) {
#pragma unroll
            for (int t = 0; t < NT; t++) {
                int c = cbase + t * 8 + 2 * tig;
                red[egrp * C_OUT + c]     = mx[t][0];
                red[egrp * C_OUT + c + 1] = mx[t][1];
            }
        }
        __syncthreads();
        for (int c = tid; c < C_OUT; c += THREADS) {
            float m = red[c];
#pragma unroll
            for (int e = 1; e < EG; e++) m = fmaxf(m, red[e * C_OUT + c]);
            float hv = (m == neg_inf()) ? 0.f : m + bias[c];
            if (FUSE) hs[c] = hv;
            else out[n * C_OUT + c] = hv;
        }
    }

    if (FUSE) {
        __syncthreads();
        if (tid < 128) {
            int half = tid >> 6;
            int j = tid & 63;
            const float* Wc = W3 + half * 128 * 64;
            float a0 = half ? 0.f : b3[j];
            float a1 = 0.f;
#pragma unroll 8
            for (int k = 0; k < 128; k += 2) {
                a0 = fmaf(hs[k],     Wc[k * 64 + j],       a0);
                a1 = fmaf(hs[k + 1], Wc[(k + 1) * 64 + j], a1);
            }
            (half ? outB : out)[n * 64 + j] = a0 + a1;
        }
    }
}

// ---------------- readout: out[i][j] = sum_n h2[n][i]*Wr[n][j] + br[j] ----------
__global__ void k_readout(const float* __restrict__ Wr, const float* __restrict__ br,
                          float* __restrict__ out) {
    __shared__ float As[16][64];
    __shared__ float Bs[16][64];
    int i0 = blockIdx.y * 64, j0 = blockIdx.x * 64;
    int tid = threadIdx.x;
    int jt = tid & 15, it = tid >> 4;
    float c[4][4];
#pragma unroll
    for (int r = 0; r < 4; r++)
#pragma unroll
        for (int s = 0; s < 4; s++) c[r][s] = 0.f;

    for (int n0 = 0; n0 < N; n0 += 16) {
        for (int idx = tid; idx < 16 * 64; idx += 256) {
            int kk = idx >> 6, col = idx & 63;
            As[kk][col] = g_h2[(n0 + kk) * 512 + i0 + col];
            Bs[kk][col] = Wr[(n0 + kk) * 512 + j0 + col];
        }
        __syncthreads();
#pragma unroll
        for (int kk = 0; kk < 16; kk++) {
            float a[4], b[4];
#pragma unroll
            for (int r = 0; r < 4; r++) a[r] = As[kk][it * 4 + r];
#pragma unroll
            for (int s = 0; s < 4; s++) b[s] = Bs[kk][jt * 4 + s];
#pragma unroll
            for (int r = 0; r < 4; r++)
#pragma unroll
                for (int s = 0; s < 4; s++) c[r][s] = fmaf(a[r], b[s], c[r][s]);
        }
        __syncthreads();
    }
#pragma unroll
    for (int r = 0; r < 4; r++)
#pragma unroll
        for (int s = 0; s < 4; s++)
            out[(i0 + it * 4 + r) * 512 + j0 + jt * 4 + s] = c[r][s] + br[j0 + jt * 4 + s];
}

extern "C" void kernel_launch(void* const* d_in, const int* in_sizes, int n_in,
                              void* d_out, int out_size) {
    const float* x  = (const float*)d_in[0];
    const void*  ei = d_in[1];
    const float* W1 = (const float*)d_in[2];
    const float* b1 = (const float*)d_in[3];
    const float* W2 = (const float*)d_in[4];
    const float* b2 = (const float*)d_in[5];
    const float* W3 = (const float*)d_in[6];
    const float* b3 = (const float*)d_in[7];
    const float* W4 = (const float*)d_in[8];
    const float* b4 = (const float*)d_in[9];
    const float* Wr = (const float*)d_in[10];
    const float* br = (const float*)d_in[11];

    int E = in_sizes[1] / 2;
    if (E > EMAX) E = EMAX;

    float *pA1, *pB1, *pA2, *pB2, *ph2;
    cudaGetSymbolAddress((void**)&pA1, g_A1);
    cudaGetSymbolAddress((void**)&pB1, g_B1);
    cudaGetSymbolAddress((void**)&pA2, g_A2);
    cudaGetSymbolAddress((void**)&pB2, g_B2);
    cudaGetSymbolAddress((void**)&ph2, g_h2);

    k_detect<<<1, 64>>>(ei);
    k_hist2<<<HB, 512>>>(ei, E);
    k_pre1<<<N, 64>>>(x, W1, b1);
    k_scanA<<<32, 512>>>();
    k_scanB<<<1, 1024>>>();
    k_scatter2<<<HB, 512>>>(ei, E);
    // conv1 (fused pre2): 1 CTA/node, 256 threads, EG=2, 3 CTAs/SM
    k_conv_mma<128, 2, 1, true, 3><<<N, 256>>>(pA1, pB1, W2, b2, pA2, pB2, W3, b3);
    // conv2: 2 CTAs/node (channel halves), 256 threads, EG=1, 3 CTAs/SM
    k_conv_mma<512, 1, 2, false, 3><<<2 * N, 256>>>(pA2, pB2, W4, b4, ph2, nullptr, nullptr, nullptr);
    k_readout<<<dim3(8, 8), 256>>>(Wr, br, (float*)d_out);
}

// round 16
// speedup vs baseline: 1.0066x; 1.0066x over previous
#include <cuda_runtime.h>
#include <cstdint>

static constexpr int N    = 1024;
static constexpr int EMAX = 524288;
static constexpr int HB   = 256;   // histogram blocks

// ---------------- device scratch ----------------
__device__ int   g_bh[HB * N];
__device__ int   g_tot[N];
__device__ int   g_base[N];
__device__ int   g_off[N + 1];
__device__ int   g_src[EMAX];
__device__ float g_A1[N * 64];
__device__ float g_B1[N * 64];
__device__ float g_A2[N * 64];
__device__ float g_B2[N * 64];
__device__ float g_h2[N * 512];

__device__ __forceinline__ float neg_inf() { return __int_as_float(0xff800000); }

// pack two fp32 into fp16x2: lo -> low half, hi -> high half
__device__ __forceinline__ uint32_t pack_h2(float lo, float hi) {
    uint32_t r;
    asm("cvt.rn.f16x2.f32 %0, %1, %2;" : "=r"(r) : "f"(hi), "f"(lo));
    return r;
}

__device__ __forceinline__ void mma_f16(float d[4], const uint4& a,
                                        const uint32_t b[2]) {
    asm volatile(
        "mma.sync.aligned.m16n8k16.row.col.f32.f16.f16.f32 "
        "{%0,%1,%2,%3}, {%4,%5,%6,%7}, {%8,%9}, {%0,%1,%2,%3};"
        : "+f"(d[0]), "+f"(d[1]), "+f"(d[2]), "+f"(d[3])
        : "r"(a.x), "r"(a.y), "r"(a.z), "r"(a.w), "r"(b[0]), "r"(b[1]));
}

// ---------------- sort pipeline ----------------
__device__ __forceinline__ int edge_val(const void* p, long long i, int is64) {
    if (is64) return (int)((const long long*)p)[i];
    return ((const int*)p)[i];
}

// In-CTA dtype detect: threads 0-63 check one int64 view value each; if edges
// are int32, some high word makes a value outside [0,N) with prob 1-(1/N)^64.
// Writes smem flag; caller must sync before and after per the pattern below.

__global__ void k_hist2(const void* edges, int E) {
    __shared__ int h[N];
    __shared__ int sis64;
    int b = blockIdx.x, tid = threadIdx.x;
    for (int i = tid; i < N; i += 512) h[i] = 0;
    if (tid == 0) sis64 = 1;
    __syncthreads();
    if (tid < 64) {
        long long v = ((const long long*)edges)[tid];
        if (v < 0 || v >= N) sis64 = 0;  // benign race: all writers store 0
    }
    __syncthreads();
    int is64 = sis64;
    int per = (E + HB - 1) / HB;
    int s0 = b * per, s1 = min(E, s0 + per);
    for (int base = s0; base < s1; base += 4096) {
        int d[8];
#pragma unroll
        for (int j = 0; j < 8; j++) {
            int e = base + tid + j * 512;
            d[j] = (e < s1) ? edge_val(edges, (long long)E + e, is64) : -1;
        }
#pragma unroll
        for (int j = 0; j < 8; j++)
            if (d[j] >= 0) atomicAdd(&h[d[j]], 1);
    }
    __syncthreads();
    for (int i = tid; i < N; i += 512) g_bh[b * N + i] = h[i];
}

// per-dst exclusive scan over the HB block-histograms.
__global__ void k_scanA() {
    __shared__ int s[16][32];
    int tid = threadIdx.x;
    int dlane = tid & 31, bg = tid >> 5;
    int d = blockIdx.x * 32 + dlane;
    int v[16], sum = 0;
#pragma unroll
    for (int j = 0; j < 16; j++) v[j] = g_bh[(bg * 16 + j) * N + d];
#pragma unroll
    for (int j = 0; j < 16; j++) { int t = v[j]; v[j] = sum; sum += t; }
    s[bg][dlane] = sum;
    __syncthreads();
    int base = 0;
#pragma unroll
    for (int k = 0; k < 16; k++) {
        int val = s[k][dlane];
        if (k < bg) base += val;
    }
    if (bg == 15) g_tot[d] = base + sum;
#pragma unroll
    for (int j = 0; j < 16; j++) g_bh[(bg * 16 + j) * N + d] = base + v[j];
}

// block 0: scan per-dst totals (1024-wide). blocks 1..64: pre1 for 16 nodes
// each (fills the chip during the otherwise single-block scan; saves a launch).
__global__ void k_scanB_pre1(const float* __restrict__ x,
                             const float* __restrict__ W1,
                             const float* __restrict__ b1) {
    if (blockIdx.x == 0) {
        __shared__ int s[N];
        int d = threadIdx.x;
        int tot = g_tot[d];
        s[d] = tot;
        __syncthreads();
        for (int off = 1; off < N; off <<= 1) {
            int v = (d >= off) ? s[d - off] : 0;
            __syncthreads();
            s[d] += v;
            __syncthreads();
        }
        g_off[d + 1] = s[d];
        if (d == 0) g_off[0] = 0;
        g_base[d] = s[d] - tot;
    } else {
        __shared__ float xr[16][64];
        int tid = threadIdx.x;
        int sub = tid >> 6, j = tid & 63;
        int n = (blockIdx.x - 1) * 16 + sub;
        xr[sub][j] = x[n * 64 + j];
        __syncthreads();
        float a = b1[j], b = 0.f;
#pragma unroll 8
        for (int k = 0; k < 64; k++) {
            float xv = xr[sub][k];
            a = fmaf(xv, W1[k * 64 + j], a);
            b = fmaf(xv, W1[(64 + k) * 64 + j], b);
        }
        g_A1[n * 64 + j] = a;
        g_B1[n * 64 + j] = b;
    }
}

__global__ void k_scatter2(const void* edges, int E) {
    __shared__ int h[N];
    __shared__ int bhs[N];
    __shared__ int sis64;
    int b = blockIdx.x, tid = threadIdx.x;
    for (int i = tid; i < N; i += 512) {
        h[i] = 0;
        bhs[i] = g_base[i] + g_bh[b * N + i];
    }
    if (tid == 0) sis64 = 1;
    __syncthreads();
    if (tid < 64) {
        long long v = ((const long long*)edges)[tid];
        if (v < 0 || v >= N) sis64 = 0;
    }
    __syncthreads();
    int is64 = sis64;
    int per = (E + HB - 1) / HB;
    int s0 = b * per, s1 = min(E, s0 + per);
    for (int base = s0; base < s1; base += 4096) {
        int d[8], sv[8];
#pragma unroll
        for (int j = 0; j < 8; j++) {
            int e = base + tid + j * 512;
            if (e < s1) {
                sv[j] = edge_val(edges, e, is64);
                d[j]  = edge_val(edges, (long long)E + e, is64);
            } else d[j] = -1;
        }
#pragma unroll
        for (int j = 0; j < 8; j++)
            if (d[j] >= 0) {
                int pos = bhs[d[j]] + atomicAdd(&h[d[j]], 1);
                g_src[pos] = sv[j];
            }
    }
}

// ---------------- tensor-core (mma.sync fp16 m16n8k16) EdgeConv ----------------
// 256 threads = 8 warps per CTA; MAXCTA CTAs co-resident per SM so one CTA's
// MMAs cover another CTA's gather/build stalls.
// SPLIT = channel-split CTAs per node (conv2: 2, each owning C_OUT/SPLIT chans).
// P tile (128 edges x 64 k, fp16) fragment-major, double-buffered:
//   uint4 slot [buf*1024 + (m*32+L)*4 + ((s+(L>>1))&3)]; rotation =>
//   conflict-free STS.128 / LDS.128.
// FUSE: epilogue computes A2/B2 = f(h1[n]) in-place (fused pre2).
template <int C_OUT, int EG, int SPLIT, bool FUSE, int MAXCTA>
__global__ void __launch_bounds__(256, MAXCTA)
k_conv_mma(const float* __restrict__ Avec, const float* __restrict__ Bvec,
           const float* __restrict__ W, const float* __restrict__ bias,
           float* __restrict__ out, float* __restrict__ outB,
           const float* __restrict__ W3, const float* __restrict__ b3) {
    constexpr int THREADS = 256;
    constexpr int CPC = C_OUT / SPLIT;
    constexpr int CG  = 8 / EG;
    constexpr int NT  = (CPC / CG) / 8;
    __shared__ __align__(16) uint4 Ps4[2048];
    __shared__ __align__(16) float avs[64];
    __shared__ float red[(EG > 1 ? EG : 1) * CPC];
    __shared__ float hs[FUSE ? 128 : 1];

    int tid = threadIdx.x, lane = tid & 31;
    int wid = tid >> 5;
    int g = lane >> 2, tig = lane & 3;
    int cgrp = wid / EG, egrp = wid % EG;
    int n = blockIdx.x / SPLIT;
    int csplit = blockIdx.x % SPLIT;
    int cbase = csplit * CPC + cgrp * (NT * 8);

    if (tid < 64) avs[tid] = Avec[n * 64 + tid];

    uint32_t wf[4][NT][2];
#pragma unroll
    for (int s = 0; s < 4; s++)
#pragma unroll
        for (int t = 0; t < NT; t++) {
            int c = cbase + t * 8 + g;
            int k0 = s * 16 + 2 * tig;
            wf[s][t][0] = pack_h2(W[k0 * C_OUT + c], W[(k0 + 1) * C_OUT + c]);
            wf[s][t][1] = pack_h2(W[(k0 + 8) * C_OUT + c], W[(k0 + 9) * C_OUT + c]);
        }

    float mx[NT][2];
#pragma unroll
    for (int t = 0; t < NT; t++) { mx[t][0] = neg_inf(); mx[t][1] = neg_inf(); }

    int beg = g_off[n], end = g_off[n + 1];

    auto build = [&](int bufi, int t0, int cnt) {
#pragma unroll
        for (int it = 0; it < 4; it++) {
            int idx = tid + it * THREADS;
            int m = idx >> 7, s = (idx >> 5) & 3, L = idx & 31;
            if (m * 16 < cnt) {
                int gg = L >> 2, tt = L & 3;
                int e0 = m * 16 + gg;
                int i0 = min(t0 + e0, end - 1);
                int i1 = min(t0 + e0 + 8, end - 1);
                const float* B0 = Bvec + g_src[i0] * 64;
                const float* B1 = Bvec + g_src[i1] * 64;
                int k0 = s * 16 + 2 * tt;
                float2 a0 = *(const float2*)(avs + k0);
                float2 a1 = *(const float2*)(avs + k0 + 8);
                float2 p0 = *(const float2*)(B0 + k0);
                float2 p1 = *(const float2*)(B1 + k0);
                float2 q0 = *(const float2*)(B0 + k0 + 8);
                float2 q1 = *(const float2*)(B1 + k0 + 8);
                uint4 v;
                v.x = pack_h2(fmaxf(a0.x + p0.x, 0.f), fmaxf(a0.y + p0.y, 0.f));
                v.y = pack_h2(fmaxf(a0.x + p1.x, 0.f), fmaxf(a0.y + p1.y, 0.f));
                v.z = pack_h2(fmaxf(a1.x + q0.x, 0.f), fmaxf(a1.y + q0.y, 0.f));
                v.w = pack_h2(fmaxf(a1.x + q1.x, 0.f), fmaxf(a1.y + q1.y, 0.f));
                Ps4[bufi * 1024 + (m * 32 + L) * 4 + ((s + (L >> 1)) & 3)] = v;
            }
        }
    };

    __syncthreads();
    if (beg < end) build(0, beg, min(128, end - beg));
    __syncthreads();

    int buf = 0;
    for (int t0 = beg; t0 < end; t0 += 128, buf ^= 1) {
        int cnt = min(128, end - t0);
        for (int m = egrp; m < 8; m += EG) {
            if (m * 16 >= cnt) break;
            float acc4[NT][4];
#pragma unroll
            for (int t = 0; t < NT; t++) {
                acc4[t][0] = 0.f; acc4[t][1] = 0.f;
                acc4[t][2] = 0.f; acc4[t][3] = 0.f;
            }
#pragma unroll
            for (int s = 0; s < 4; s++) {
                uint4 q = Ps4[buf * 1024 + (m * 32 + lane) * 4 + ((s + (lane >> 1)) & 3)];
#pragma unroll
                for (int t = 0; t < NT; t++) mma_f16(acc4[t], q, wf[s][t]);
            }
            int r0 = m * 16 + g;
            bool v0 = r0 < cnt, v1 = (r0 + 8) < cnt;
#pragma unroll
            for (int t = 0; t < NT; t++) {
                if (v0) { mx[t][0] = fmaxf(mx[t][0], acc4[t][0]);
                          mx[t][1] = fmaxf(mx[t][1], acc4[t][1]); }
                if (v1) { mx[t][0] = fmaxf(mx[t][0], acc4[t][2]);
                          mx[t][1] = fmaxf(mx[t][1], acc4[t][3]); }
            }
        }
        int nt0 = t0 + 128;
        if (nt0 < end) build(buf ^ 1, nt0, min(128, end - nt0));
        __syncthreads();
    }

#pragma unroll
    for (int t = 0; t < NT; t++)
#pragma unroll
        for (int off = 4; off < 32; off <<= 1) {
            mx[t][0] = fmaxf(mx[t][0], __shfl_xor_sync(0xffffffffu, mx[t][0], off));
            mx[t][1] = fmaxf(mx[t][1], __shfl_xor_sync(0xffffffffu, mx[t][1], off));
        }

    if (EG == 1) {
        if (lane < 4) {
#pragma unroll
            for (int t = 0; t < NT; t++) {
                int c = cbase + t * 8 + 2 * tig;
                float v0 = mx[t][0], v1 = mx[t][1];
                out[n * C_OUT + c]     = (v0 == neg_inf()) ? 0.f : v0 + bias[c];
                out[n * C_OUT + c + 1] = (v1 == neg_inf()) ? 0.f : v1 + bias[c + 1];
            }
        }
    } else {
        if (lane < 4) {
#pragma unroll
            for (int t = 0; t < NT; t++) {
                int c = cbase + t * 8 + 2 * tig;
                red[egrp * C_OUT + c]     = mx[t][0];
                red[egrp * C_OUT + c + 1] = mx[t][1];
            }
        }
        __syncthreads();
        for (int c = tid; c < C_OUT; c += THREADS) {
            float m = red[c];
#pragma unroll
            for (int e = 1; e < EG; e++) m = fmaxf(m, red[e * C_OUT + c]);
            float hv = (m == neg_inf()) ? 0.f : m + bias[c];
            if (FUSE) hs[c] = hv;
            else out[n * C_OUT + c] = hv;
        }
    }

    if (FUSE) {
        __syncthreads();
        if (tid < 128) {
            int half = tid >> 6;
            int j = tid & 63;
            const float* Wc = W3 + half * 128 * 64;
            float a0 = half ? 0.f : b3[j];
            float a1 = 0.f;
#pragma unroll 8
            for (int k = 0; k < 128; k += 2) {
                a0 = fmaf(hs[k],     Wc[k * 64 + j],       a0);
                a1 = fmaf(hs[k + 1], Wc[(k + 1) * 64 + j], a1);
            }
            (half ? outB : out)[n * 64 + j] = a0 + a1;
        }
    }
}

// ---------------- readout: out[i][j] = sum_n h2[n][i]*Wr[n][j] + br[j] ----------
__global__ void k_readout(const float* __restrict__ Wr, const float* __restrict__ br,
                          float* __restrict__ out) {
    __shared__ float As[16][64];
    __shared__ float Bs[16][64];
    int i0 = blockIdx.y * 64, j0 = blockIdx.x * 64;
    int tid = threadIdx.x;
    int jt = tid & 15, it = tid >> 4;
    float c[4][4];
#pragma unroll
    for (int r = 0; r < 4; r++)
#pragma unroll
        for (int s = 0; s < 4; s++) c[r][s] = 0.f;

    for (int n0 = 0; n0 < N; n0 += 16) {
        for (int idx = tid; idx < 16 * 64; idx += 256) {
            int kk = idx >> 6, col = idx & 63;
            As[kk][col] = g_h2[(n0 + kk) * 512 + i0 + col];
            Bs[kk][col] = Wr[(n0 + kk) * 512 + j0 + col];
        }
        __syncthreads();
#pragma unroll
        for (int kk = 0; kk < 16; kk++) {
            float a[4], b[4];
#pragma unroll
            for (int r = 0; r < 4; r++) a[r] = As[kk][it * 4 + r];
#pragma unroll
            for (int s = 0; s < 4; s++) b[s] = Bs[kk][jt * 4 + s];
#pragma unroll
            for (int r = 0; r < 4; r++)
#pragma unroll
                for (int s = 0; s < 4; s++) c[r][s] = fmaf(a[r], b[s], c[r][s]);
        }
        __syncthreads();
    }
#pragma unroll
    for (int r = 0; r < 4; r++)
#pragma unroll
        for (int s = 0; s < 4; s++)
            out[(i0 + it * 4 + r) * 512 + j0 + jt * 4 + s] = c[r][s] + br[j0 + jt * 4 + s];
}

extern "C" void kernel_launch(void* const* d_in, const int* in_sizes, int n_in,
                              void* d_out, int out_size) {
    const float* x  = (const float*)d_in[0];
    const void*  ei = d_in[1];
    const float* W1 = (const float*)d_in[2];
    const float* b1 = (const float*)d_in[3];
    const float* W2 = (const float*)d_in[4];
    const float* b2 = (const float*)d_in[5];
    const float* W3 = (const float*)d_in[6];
    const float* b3 = (const float*)d_in[7];
    const float* W4 = (const float*)d_in[8];
    const float* b4 = (const float*)d_in[9];
    const float* Wr = (const float*)d_in[10];
    const float* br = (const float*)d_in[11];

    int E = in_sizes[1] / 2;
    if (E > EMAX) E = EMAX;

    float *pA1, *pB1, *pA2, *pB2, *ph2;
    cudaGetSymbolAddress((void**)&pA1, g_A1);
    cudaGetSymbolAddress((void**)&pB1, g_B1);
    cudaGetSymbolAddress((void**)&pA2, g_A2);
    cudaGetSymbolAddress((void**)&pB2, g_B2);
    cudaGetSymbolAddress((void**)&ph2, g_h2);

    k_hist2<<<HB, 512>>>(ei, E);                 // idx 0
    k_scanA<<<32, 512>>>();                      // idx 1
    k_scanB_pre1<<<65, 1024>>>(x, W1, b1);       // idx 2 (scan + pre1 fused)
    k_scatter2<<<HB, 512>>>(ei, E);              // idx 3 <- profiled
    // conv1 (fused pre2): 1 CTA/node, 256 threads, EG=2, 3 CTAs/SM
    k_conv_mma<128, 2, 1, true, 3><<<N, 256>>>(pA1, pB1, W2, b2, pA2, pB2, W3, b3);
    // conv2: 2 CTAs/node (channel halves), 256 threads, EG=1, 3 CTAs/SM
    k_conv_mma<512, 1, 2, false, 3><<<2 * N, 256>>>(pA2, pB2, W4, b4, ph2, nullptr, nullptr, nullptr);
    k_readout<<<dim3(8, 8), 256>>>(Wr, br, (float*)d_out);
}

// round 17
// speedup vs baseline: 1.0091x; 1.0024x over previous
#include <cuda_runtime.h>
#include <cstdint>

static constexpr int N    = 1024;
static constexpr int EMAX = 524288;
static constexpr int HB   = 256;   // histogram blocks

// ---------------- device scratch ----------------
__device__ int   g_alloc;
__device__ int   g_bh[HB * N];
__device__ int   g_basev[N];
__device__ int   g_cnt[N];
__device__ int   g_src[EMAX];
__device__ float g_A1[N * 64];
__device__ float g_B1[N * 64];
__device__ float g_A2[N * 64];
__device__ float g_B2[N * 64];
__device__ float g_h2[N * 512];

__device__ __forceinline__ float neg_inf() { return __int_as_float(0xff800000); }

// pack two fp32 into fp16x2: lo -> low half, hi -> high half
__device__ __forceinline__ uint32_t pack_h2(float lo, float hi) {
    uint32_t r;
    asm("cvt.rn.f16x2.f32 %0, %1, %2;" : "=r"(r) : "f"(hi), "f"(lo));
    return r;
}

__device__ __forceinline__ void mma_f16(float d[4], const uint4& a,
                                        const uint32_t b[2]) {
    asm volatile(
        "mma.sync.aligned.m16n8k16.row.col.f32.f16.f16.f32 "
        "{%0,%1,%2,%3}, {%4,%5,%6,%7}, {%8,%9}, {%0,%1,%2,%3};"
        : "+f"(d[0]), "+f"(d[1]), "+f"(d[2]), "+f"(d[3])
        : "r"(a.x), "r"(a.y), "r"(a.z), "r"(a.w), "r"(b[0]), "r"(b[1]));
}

// ---------------- sort pipeline ----------------
__device__ __forceinline__ int edge_val(const void* p, long long i, int is64) {
    if (is64) return (int)((const long long*)p)[i];
    return ((const int*)p)[i];
}

// blocks [0, HB): per-block histogram of dst. blocks [HB, HB+128): pre1
// (8 nodes per block). Block HB also resets the bucket allocator (graph-safe).
__global__ void k_hist_pre1(const void* edges, int E,
                            const float* __restrict__ x,
                            const float* __restrict__ W1,
                            const float* __restrict__ b1) {
    int b = blockIdx.x, tid = threadIdx.x;
    if (b >= HB) {
        // ---- pre1: A1/B1 for 8 nodes ----
        if (b == HB && tid == 0) g_alloc = 0;
        __shared__ float xr[8][64];
        int sub = tid >> 6, j = tid & 63;
        int n = (b - HB) * 8 + sub;
        xr[sub][j] = x[n * 64 + j];
        __syncthreads();
        float a = b1[j], bb = 0.f;
#pragma unroll 8
        for (int k = 0; k < 64; k++) {
            float xv = xr[sub][k];
            a  = fmaf(xv, W1[k * 64 + j], a);
            bb = fmaf(xv, W1[(64 + k) * 64 + j], bb);
        }
        g_A1[n * 64 + j] = a;
        g_B1[n * 64 + j] = bb;
        return;
    }
    // ---- histogram ----
    __shared__ int h[N];
    __shared__ int sis64;
    for (int i = tid; i < N; i += 512) h[i] = 0;
    if (tid == 0) sis64 = 1;
    __syncthreads();
    if (tid < 64) {
        long long v = ((const long long*)edges)[tid];
        if (v < 0 || v >= N) sis64 = 0;  // benign race: all writers store 0
    }
    __syncthreads();
    int is64 = sis64;
    int per = (E + HB - 1) / HB;
    int s0 = b * per, s1 = min(E, s0 + per);
    for (int base = s0; base < s1; base += 4096) {
        int d[8];
#pragma unroll
        for (int j = 0; j < 8; j++) {
            int e = base + tid + j * 512;
            d[j] = (e < s1) ? edge_val(edges, (long long)E + e, is64) : -1;
        }
#pragma unroll
        for (int j = 0; j < 8; j++)
            if (d[j] >= 0) atomicAdd(&h[d[j]], 1);
    }
    __syncthreads();
    for (int i = tid; i < N; i += 512) g_bh[b * N + i] = h[i];
}

// per-dst exclusive scan over the HB block-histograms + order-free base
// allocation via atomicAdd (buckets need only be contiguous per dst; the max
// aggregation is exactly commutative, so bucket placement doesn't matter).
__global__ void k_scanA_alloc() {
    __shared__ int s[16][32];
    int tid = threadIdx.x;
    int dlane = tid & 31, bg = tid >> 5;
    int d = blockIdx.x * 32 + dlane;
    int v[16], sum = 0;
#pragma unroll
    for (int j = 0; j < 16; j++) v[j] = g_bh[(bg * 16 + j) * N + d];
#pragma unroll
    for (int j = 0; j < 16; j++) { int t = v[j]; v[j] = sum; sum += t; }
    s[bg][dlane] = sum;
    __syncthreads();
    int base = 0;
#pragma unroll
    for (int k = 0; k < 16; k++) {
        int val = s[k][dlane];
        if (k < bg) base += val;
    }
    if (bg == 15) {
        int tot = base + sum;
        g_cnt[d] = tot;
        g_basev[d] = atomicAdd(&g_alloc, tot);
    }
#pragma unroll
    for (int j = 0; j < 16; j++) g_bh[(bg * 16 + j) * N + d] = base + v[j];
}

__global__ void k_scatter2(const void* edges, int E) {
    __shared__ int h[N];
    __shared__ int bhs[N];
    __shared__ int sis64;
    int b = blockIdx.x, tid = threadIdx.x;
    for (int i = tid; i < N; i += 512) {
        h[i] = 0;
        bhs[i] = g_basev[i] + g_bh[b * N + i];
    }
    if (tid == 0) sis64 = 1;
    __syncthreads();
    if (tid < 64) {
        long long v = ((const long long*)edges)[tid];
        if (v < 0 || v >= N) sis64 = 0;
    }
    __syncthreads();
    int is64 = sis64;
    int per = (E + HB - 1) / HB;
    int s0 = b * per, s1 = min(E, s0 + per);
    for (int base = s0; base < s1; base += 4096) {
        int d[8], sv[8];
#pragma unroll
        for (int j = 0; j < 8; j++) {
            int e = base + tid + j * 512;
            if (e < s1) {
                sv[j] = edge_val(edges, e, is64);
                d[j]  = edge_val(edges, (long long)E + e, is64);
            } else d[j] = -1;
        }
#pragma unroll
        for (int j = 0; j < 8; j++)
            if (d[j] >= 0) {
                int pos = bhs[d[j]] + atomicAdd(&h[d[j]], 1);
                g_src[pos] = sv[j];
            }
    }
}

// ---------------- tensor-core (mma.sync fp16 m16n8k16) EdgeConv ----------------
// 256 threads = 8 warps per CTA; MAXCTA CTAs co-resident per SM so one CTA's
// MMAs cover another CTA's gather/build stalls.
// SPLIT = channel-split CTAs per node (conv2: 2, each owning C_OUT/SPLIT chans).
// P tile (128 edges x 64 k, fp16) fragment-major, double-buffered:
//   uint4 slot [buf*1024 + (m*32+L)*4 + ((s+(L>>1))&3)]; rotation =>
//   conflict-free STS.128 / LDS.128.
// FUSE: epilogue computes A2/B2 = f(h1[n]) in-place (fused pre2).
template <int C_OUT, int EG, int SPLIT, bool FUSE, int MAXCTA>
__global__ void __launch_bounds__(256, MAXCTA)
k_conv_mma(const float* __restrict__ Avec, const float* __restrict__ Bvec,
           const float* __restrict__ W, const float* __restrict__ bias,
           float* __restrict__ out, float* __restrict__ outB,
           const float* __restrict__ W3, const float* __restrict__ b3) {
    constexpr int THREADS = 256;
    constexpr int CPC = C_OUT / SPLIT;
    constexpr int CG  = 8 / EG;
    constexpr int NT  = (CPC / CG) / 8;
    __shared__ __align__(16) uint4 Ps4[2048];
    __shared__ __align__(16) float avs[64];
    __shared__ float red[(EG > 1 ? EG : 1) * CPC];
    __shared__ float hs[FUSE ? 128 : 1];

    int tid = threadIdx.x, lane = tid & 31;
    int wid = tid >> 5;
    int g = lane >> 2, tig = lane & 3;
    int cgrp = wid / EG, egrp = wid % EG;
    int n = blockIdx.x / SPLIT;
    int csplit = blockIdx.x % SPLIT;
    int cbase = csplit * CPC + cgrp * (NT * 8);

    if (tid < 64) avs[tid] = Avec[n * 64 + tid];

    uint32_t wf[4][NT][2];
#pragma unroll
    for (int s = 0; s < 4; s++)
#pragma unroll
        for (int t = 0; t < NT; t++) {
            int c = cbase + t * 8 + g;
            int k0 = s * 16 + 2 * tig;
            wf[s][t][0] = pack_h2(W[k0 * C_OUT + c], W[(k0 + 1) * C_OUT + c]);
            wf[s][t][1] = pack_h2(W[(k0 + 8) * C_OUT + c], W[(k0 + 9) * C_OUT + c]);
        }

    float mx[NT][2];
#pragma unroll
    for (int t = 0; t < NT; t++) { mx[t][0] = neg_inf(); mx[t][1] = neg_inf(); }

    int beg = g_basev[n];
    int end = beg + g_cnt[n];

    auto build = [&](int bufi, int t0, int cnt) {
#pragma unroll
        for (int it = 0; it < 4; it++) {
            int idx = tid + it * THREADS;
            int m = idx >> 7, s = (idx >> 5) & 3, L = idx & 31;
            if (m * 16 < cnt) {
                int gg = L >> 2, tt = L & 3;
                int e0 = m * 16 + gg;
                int i0 = min(t0 + e0, end - 1);
                int i1 = min(t0 + e0 + 8, end - 1);
                const float* B0 = Bvec + g_src[i0] * 64;
                const float* B1 = Bvec + g_src[i1] * 64;
                int k0 = s * 16 + 2 * tt;
                float2 a0 = *(const float2*)(avs + k0);
                float2 a1 = *(const float2*)(avs + k0 + 8);
                float2 p0 = *(const float2*)(B0 + k0);
                float2 p1 = *(const float2*)(B1 + k0);
                float2 q0 = *(const float2*)(B0 + k0 + 8);
                float2 q1 = *(const float2*)(B1 + k0 + 8);
                uint4 v;
                v.x = pack_h2(fmaxf(a0.x + p0.x, 0.f), fmaxf(a0.y + p0.y, 0.f));
                v.y = pack_h2(fmaxf(a0.x + p1.x, 0.f), fmaxf(a0.y + p1.y, 0.f));
                v.z = pack_h2(fmaxf(a1.x + q0.x, 0.f), fmaxf(a1.y + q0.y, 0.f));
                v.w = pack_h2(fmaxf(a1.x + q1.x, 0.f), fmaxf(a1.y + q1.y, 0.f));
                Ps4[bufi * 1024 + (m * 32 + L) * 4 + ((s + (L >> 1)) & 3)] = v;
            }
        }
    };

    __syncthreads();
    if (beg < end) build(0, beg, min(128, end - beg));
    __syncthreads();

    int buf = 0;
    for (int t0 = beg; t0 < end; t0 += 128, buf ^= 1) {
        int cnt = min(128, end - t0);
        for (int m = egrp; m < 8; m += EG) {
            if (m * 16 >= cnt) break;
            float acc4[NT][4];
#pragma unroll
            for (int t = 0; t < NT; t++) {
                acc4[t][0] = 0.f; acc4[t][1] = 0.f;
                acc4[t][2] = 0.f; acc4[t][3] = 0.f;
            }
#pragma unroll
            for (int s = 0; s < 4; s++) {
                uint4 q = Ps4[buf * 1024 + (m * 32 + lane) * 4 + ((s + (lane >> 1)) & 3)];
#pragma unroll
                for (int t = 0; t < NT; t++) mma_f16(acc4[t], q, wf[s][t]);
            }
            int r0 = m * 16 + g;
            bool v0 = r0 < cnt, v1 = (r0 + 8) < cnt;
#pragma unroll
            for (int t = 0; t < NT; t++) {
                if (v0) { mx[t][0] = fmaxf(mx[t][0], acc4[t][0]);
                          mx[t][1] = fmaxf(mx[t][1], acc4[t][1]); }
                if (v1) { mx[t][0] = fmaxf(mx[t][0], acc4[t][2]);
                          mx[t][1] = fmaxf(mx[t][1], acc4[t][3]); }
            }
        }
        int nt0 = t0 + 128;
        if (nt0 < end) build(buf ^ 1, nt0, min(128, end - nt0));
        __syncthreads();
    }

#pragma unroll
    for (int t = 0; t < NT; t++)
#pragma unroll
        for (int off = 4; off < 32; off <<= 1) {
            mx[t][0] = fmaxf(mx[t][0], __shfl_xor_sync(0xffffffffu, mx[t][0], off));
            mx[t][1] = fmaxf(mx[t][1], __shfl_xor_sync(0xffffffffu, mx[t][1], off));
        }

    if (EG == 1) {
        if (lane < 4) {
#pragma unroll
            for (int t = 0; t < NT; t++) {
                int c = cbase + t * 8 + 2 * tig;
                float v0 = mx[t][0], v1 = mx[t][1];
                out[n * C_OUT + c]     = (v0 == neg_inf()) ? 0.f : v0 + bias[c];
                out[n * C_OUT + c + 1] = (v1 == neg_inf()) ? 0.f : v1 + bias[c + 1];
            }
        }
    } else {
        if (lane < 4) {
#pragma unroll
            for (int t = 0; t < NT; t++) {
                int c = cbase + t * 8 + 2 * tig;
                red[egrp * C_OUT + c]     = mx[t][0];
                red[egrp * C_OUT + c + 1] = mx[t][1];
            }
        }
        __syncthreads();
        for (int c = tid; c < C_OUT; c += THREADS) {
            float m = red[c];
#pragma unroll
            for (int e = 1; e < EG; e++) m = fmaxf(m, red[e * C_OUT + c]);
            float hv = (m == neg_inf()) ? 0.f : m + bias[c];
            if (FUSE) hs[c] = hv;
            else out[n * C_OUT + c] = hv;
        }
    }

    if (FUSE) {
        __syncthreads();
        if (tid < 128) {
            int half = tid >> 6;
            int j = tid & 63;
            const float* Wc = W3 + half * 128 * 64;
            float a0 = half ? 0.f : b3[j];
            float a1 = 0.f;
#pragma unroll 8
            for (int k = 0; k < 128; k += 2) {
                a0 = fmaf(hs[k],     Wc[k * 64 + j],       a0);
                a1 = fmaf(hs[k + 1], Wc[(k + 1) * 64 + j], a1);
            }
            (half ? outB : out)[n * 64 + j] = a0 + a1;
        }
    }
}

// ---------------- readout: out[i][j] = sum_n h2[n][i]*Wr[n][j] + br[j] ----------
__global__ void k_readout(const float* __restrict__ Wr, const float* __restrict__ br,
                          float* __restrict__ out) {
    __shared__ float As[16][64];
    __shared__ float Bs[16][64];
    int i0 = blockIdx.y * 64, j0 = blockIdx.x * 64;
    int tid = threadIdx.x;
    int jt = tid & 15, it = tid >> 4;
    float c[4][4];
#pragma unroll
    for (int r = 0; r < 4; r++)
#pragma unroll
        for (int s = 0; s < 4; s++) c[r][s] = 0.f;

    for (int n0 = 0; n0 < N; n0 += 16) {
        for (int idx = tid; idx < 16 * 64; idx += 256) {
            int kk = idx >> 6, col = idx & 63;
            As[kk][col] = g_h2[(n0 + kk) * 512 + i0 + col];
            Bs[kk][col] = Wr[(n0 + kk) * 512 + j0 + col];
        }
        __syncthreads();
#pragma unroll
        for (int kk = 0; kk < 16; kk++) {
            float a[4], b[4];
#pragma unroll
            for (int r = 0; r < 4; r++) a[r] = As[kk][it * 4 + r];
#pragma unroll
            for (int s = 0; s < 4; s++) b[s] = Bs[kk][jt * 4 + s];
#pragma unroll
            for (int r = 0; r < 4; r++)
#pragma unroll
                for (int s = 0; s < 4; s++) c[r][s] = fmaf(a[r], b[s], c[r][s]);
        }
        __syncthreads();
    }
#pragma unroll
    for (int r = 0; r < 4; r++)
#pragma unroll
        for (int s = 0; s < 4; s++)
            out[(i0 + it * 4 + r) * 512 + j0 + jt * 4 + s] = c[r][s] + br[j0 + jt * 4 + s];
}

extern "C" void kernel_launch(void* const* d_in, const int* in_sizes, int n_in,
                              void* d_out, int out_size) {
    const float* x  = (const float*)d_in[0];
    const void*  ei = d_in[1];
    const float* W1 = (const float*)d_in[2];
    const float* b1 = (const float*)d_in[3];
    const float* W2 = (const float*)d_in[4];
    const float* b2 = (const float*)d_in[5];
    const float* W3 = (const float*)d_in[6];
    const float* b3 = (const float*)d_in[7];
    const float* W4 = (const float*)d_in[8];
    const float* b4 = (const float*)d_in[9];
    const float* Wr = (const float*)d_in[10];
    const float* br = (const float*)d_in[11];

    int E = in_sizes[1] / 2;
    if (E > EMAX) E = EMAX;

    float *pA1, *pB1, *pA2, *pB2, *ph2;
    cudaGetSymbolAddress((void**)&pA1, g_A1);
    cudaGetSymbolAddress((void**)&pB1, g_B1);
    cudaGetSymbolAddress((void**)&pA2, g_A2);
    cudaGetSymbolAddress((void**)&pB2, g_B2);
    cudaGetSymbolAddress((void**)&ph2, g_h2);

    k_hist_pre1<<<HB + 128, 512>>>(ei, E, x, W1, b1);   // idx 0 (hist + pre1)
    k_scanA_alloc<<<32, 512>>>();                       // idx 1
    k_scatter2<<<HB, 512>>>(ei, E);                     // idx 2
    // conv1 (fused pre2): idx 3 <- profiled
    k_conv_mma<128, 2, 1, true, 3><<<N, 256>>>(pA1, pB1, W2, b2, pA2, pB2, W3, b3);
    // conv2: 2 CTAs/node (channel halves), 256 threads, EG=1, 3 CTAs/SM
    k_conv_mma<512, 1, 2, false, 3><<<2 * N, 256>>>(pA2, pB2, W4, b4, ph2, nullptr, nullptr, nullptr);
    k_readout<<<dim3(8, 8), 256>>>(Wr, br, (float*)d_out);
}